// round 16
// baseline (speedup 1.0000x reference)
#include <cuda_runtime.h>
#include <cuda_bf16.h>
#include <cuda_fp16.h>
#include <mma.h>
#include <cstdint>

using namespace nvcuda;

#define NN 50000
#define NE 800000
#define NG 512
#define DD 64
#define DOUT 32
#define LN_EPS 1e-5f
#define MM_ROWS 128

// ---------------- scratch (static device globals; 16B aligned) --------------
__device__ int g_is64;                            // 1 if index inputs are int64
__device__ int g_alloc;                           // CSR allocation cursor
__device__ __align__(16) int      g_edeg[NN];     // edge in-degree (no self loop)
__device__ __align__(16) float    g_dinv[NN];
__device__ __align__(16) int      g_src[NE];
__device__ __align__(16) int      g_dst[NE];
__device__ __align__(16) int      g_rank[NE];     // edge's rank within its dst row
__device__ __align__(16) int      g_rowstart[NN]; // CSR row offsets (unordered alloc)
__device__ __align__(16) uint16_t g_csr[NE];      // CSR: src node (u16; NN < 65536)
__device__ __align__(16) __half   g_h[NN * DD];   // layer activations (fp16)
__device__ __align__(16) __half   g_hw[NN * DD];  // h @ W (fp16)
__device__ __align__(16) float    g_pool[NG * DD];
__device__ __align__(16) float    g_cnt[NG];

// ---------------- helpers ---------------------------------------------------
__device__ __forceinline__ float warp_sum(float v) {
    #pragma unroll
    for (int o = 16; o > 0; o >>= 1) v += __shfl_xor_sync(0xffffffffu, v, o);
    return v;
}
__device__ __forceinline__ int clampi(int v, int hi) {   // [0, hi)
    return v < 0 ? 0 : (v >= hi ? hi - 1 : v);
}
__device__ __forceinline__ int read_idx(const void* p, int i) {
    if (g_is64) return (int)((const long long*)p)[i];
    return ((const int*)p)[i];
}

// ---------------- setup kernels ---------------------------------------------
__global__ void k_prep(const int* __restrict__ raw) {
    int i = blockIdx.x * blockDim.x + threadIdx.x;
    if (i < NN) g_edeg[i] = 0;
    if (i < NG) g_cnt[i] = 0.0f;
    if (i == 0) g_alloc = 0;
    if (blockIdx.x == 0) {
        __shared__ int any;
        if (threadIdx.x == 0) any = 0;
        __syncthreads();
        if (raw[2 * threadIdx.x + 1] != 0) atomicOr(&any, 1);
        __syncthreads();
        if (threadIdx.x == 0) g_is64 = (any == 0) ? 1 : 0;
    }
}

// histogram; the returned old count IS this edge's stable rank in its dst row.
__global__ void k_deg(const void* __restrict__ ei) {
    int e = blockIdx.x * blockDim.x + threadIdx.x;
    if (e >= NE) return;
    int s = clampi(read_idx(ei, e), NN);
    int d = clampi(read_idx(ei, NE + e), NN);
    g_src[e] = s;
    g_dst[e] = d;
    g_rank[e] = atomicAdd(&g_edeg[d], 1);
}

// CSR slot allocation (order-free) + dinv + pool zero.
__global__ void k_alloc(const void* __restrict__ batch) {
    int i = blockIdx.x * blockDim.x + threadIdx.x;
    if (i < NG * DD) g_pool[i] = 0.0f;
    if (i >= NN) return;
    int d = g_edeg[i];
    g_dinv[i] = rsqrtf((float)(d + 1));   // +1 self loop
    g_rowstart[i] = atomicAdd(&g_alloc, d);
}

// atomic-free bucket: pos = rowstart[dst] + rank; store src only (2B).
__global__ void k_bucket() {
    int e = blockIdx.x * blockDim.x + threadIdx.x;
    if (e >= NE) return;
    int d = g_dst[e];
    int pos = g_rowstart[d] + g_rank[e];
    g_csr[pos] = (uint16_t)g_src[e];
}

// ---------------- GEMM: g_hw = in @ W via wmma (HMMA fp16 -> fp32 acc) ------
__global__ void k_matmul(int use_h, const float* __restrict__ xin,
                         const float* __restrict__ W) {
    __shared__ __align__(16) char sbuf[128 * 72 * 4];
    __half (*As)[72] = reinterpret_cast<__half (*)[72]>(sbuf);
    __half (*Bs)[72] = reinterpret_cast<__half (*)[72]>(sbuf + 128 * 72 * 2);
    float  (*Cs)[72] = reinterpret_cast<float  (*)[72]>(sbuf);

    int t = threadIdx.x;
    int base = blockIdx.x * MM_ROWS;
    int row = t >> 1;
    int part = (t & 1) * 32;
    int grow = base + row;

    if (grow < NN) {
        if (use_h) {
            const int4* src = reinterpret_cast<const int4*>(&g_h[grow * DD + part]);
            int4* dst = reinterpret_cast<int4*>(&As[row][part]);
            #pragma unroll
            for (int i = 0; i < 4; i++) dst[i] = src[i];
        } else {
            const float4* src = reinterpret_cast<const float4*>(&xin[grow * DD + part]);
            __half2* dst = reinterpret_cast<__half2*>(&As[row][part]);
            #pragma unroll
            for (int i = 0; i < 8; i++) {
                float4 v = src[i];
                dst[2 * i]     = __floats2half2_rn(v.x, v.y);
                dst[2 * i + 1] = __floats2half2_rn(v.z, v.w);
            }
        }
    } else {
        int4 z = make_int4(0, 0, 0, 0);
        int4* dst = reinterpret_cast<int4*>(&As[row][part]);
        #pragma unroll
        for (int i = 0; i < 4; i++) dst[i] = z;
    }
    if (t < 128) {
        int brow = t >> 1;
        int bpart = (t & 1) * 32;
        const float4* src = reinterpret_cast<const float4*>(&W[brow * DD + bpart]);
        __half2* dst = reinterpret_cast<__half2*>(&Bs[brow][bpart]);
        #pragma unroll
        for (int i = 0; i < 8; i++) {
            float4 v = src[i];
            dst[2 * i]     = __floats2half2_rn(v.x, v.y);
            dst[2 * i + 1] = __floats2half2_rn(v.z, v.w);
        }
    }
    __syncthreads();

    int w = t >> 5;
    wmma::fragment<wmma::accumulator, 16, 16, 16, float> acc[4];
    #pragma unroll
    for (int n = 0; n < 4; n++) wmma::fill_fragment(acc[n], 0.0f);
    #pragma unroll
    for (int k = 0; k < 4; k++) {
        wmma::fragment<wmma::matrix_a, 16, 16, 16, __half, wmma::row_major> af;
        wmma::load_matrix_sync(af, &As[w * 16][k * 16], 72);
        #pragma unroll
        for (int n = 0; n < 4; n++) {
            wmma::fragment<wmma::matrix_b, 16, 16, 16, __half, wmma::row_major> bf;
            wmma::load_matrix_sync(bf, &Bs[k * 16][n * 16], 72);
            wmma::mma_sync(acc[n], af, bf, acc[n]);
        }
    }
    __syncthreads();
    #pragma unroll
    for (int n = 0; n < 4; n++)
        wmma::store_matrix_sync(&Cs[w * 16][n * 16], acc[n], 72, wmma::mem_row_major);
    __syncthreads();

    if (grow < NN) {
        __half2* dst = reinterpret_cast<__half2*>(&g_hw[grow * DD + part]);
        #pragma unroll
        for (int i = 0; i < 16; i++)
            dst[i] = __floats2half2_rn(Cs[row][part + 2 * i], Cs[row][part + 2 * i + 1]);
    }
}

// ---------------- fused gather + bias + LN + ReLU (+ pool on last) ----------
// one warp per node; lane handles cols 2*lane, 2*lane+1. No smem, no barriers.
// Edge weight computed on the fly: dinv is L1/L2-resident (200 KB).
__global__ void k_gather_ln(const float* __restrict__ b,
                            const float* __restrict__ lw,
                            const float* __restrict__ lb,
                            int last, const void* __restrict__ batch) {
    int n = (blockIdx.x * blockDim.x + threadIdx.x) >> 5;
    int lane = threadIdx.x & 31;
    if (n >= NN) return;

    const __half2* hw2 = reinterpret_cast<const __half2*>(g_hw);

    float dn = g_dinv[n];
    float2 bb = reinterpret_cast<const float2*>(b)[lane];
    float2 self = __half22float2(hw2[n * 32 + lane]);
    float a0 = bb.x + dn * dn * self.x;
    float a1 = bb.y + dn * dn * self.y;

    int beg = g_rowstart[n];
    int cnt = g_edeg[n];
    #pragma unroll 4
    for (int j = 0; j < cnt; j++) {
        int s = (int)g_csr[beg + j];
        float w = g_dinv[s] * dn;
        float2 v = __half22float2(hw2[s * 32 + lane]);
        a0 += w * v.x;
        a1 += w * v.y;
    }

    float mu = warp_sum(a0 + a1) * (1.0f / DD);
    float d0 = a0 - mu, d1 = a1 - mu;
    float var = warp_sum(d0 * d0 + d1 * d1) * (1.0f / DD);
    float rs = rsqrtf(var + LN_EPS);
    float2 w2 = reinterpret_cast<const float2*>(lw)[lane];
    float2 lb2 = reinterpret_cast<const float2*>(lb)[lane];
    float o0 = fmaxf(d0 * rs * w2.x + lb2.x, 0.0f);
    float o1 = fmaxf(d1 * rs * w2.y + lb2.y, 0.0f);
    reinterpret_cast<__half2*>(g_h)[n * 32 + lane] = __floats2half2_rn(o0, o1);

    if (last) {
        int g = clampi(read_idx(batch, n), NG);
        atomicAdd(&g_pool[g * DD + 2 * lane],     o0);
        atomicAdd(&g_pool[g * DD + 2 * lane + 1], o1);
    }
}

// ---------------- output projection ------------------------------------------
__global__ void k_final(const float* __restrict__ Wo, const float* __restrict__ bo,
                        float* __restrict__ out) {
    int g = blockIdx.x;
    int j = threadIdx.x;          // 0..31
    float inv = 1.0f / fmaxf(g_cnt[g], 1.0f);
    float acc = bo[j];
    #pragma unroll
    for (int k = 0; k < DD; k++)
        acc += g_pool[g * DD + k] * inv * Wo[k * DOUT + j];
    out[g * DOUT + j] = acc;
}

// batch histogram (separated from alloc so alloc stays node-only)
__global__ void k_cnt(const void* __restrict__ batch) {
    int i = blockIdx.x * blockDim.x + threadIdx.x;
    if (i < NN) atomicAdd(&g_cnt[clampi(read_idx(batch, i), NG)], 1.0f);
}

// ---------------- launch -----------------------------------------------------
extern "C" void kernel_launch(void* const* d_in, const int* in_sizes, int n_in,
                              void* d_out, int out_size) {
    const float* x      = (const float*)d_in[0];
    const void*  ei     = d_in[1];                 // int32 or int64 (probed)
    const void*  batch  = d_in[2];
    const float* W_in   = (const float*)d_in[3];
    const float* b_in   = (const float*)d_in[4];
    const float* ln_in_w= (const float*)d_in[5];
    const float* ln_in_b= (const float*)d_in[6];
    const float* W_h    = (const float*)d_in[7];   // [2,64,64]
    const float* b_h    = (const float*)d_in[8];   // [2,64]
    const float* ln_h_w = (const float*)d_in[9];   // [2,64]
    const float* ln_h_b = (const float*)d_in[10];  // [2,64]
    const float* W_out  = (const float*)d_in[11];
    const float* b_out  = (const float*)d_in[12];
    float* out = (float*)d_out;

    const int T = 256;
    const int nGrid = (NN + T - 1) / T;
    const int eGrid = (NE + T - 1) / T;

    // CSR + norm build (once per call)
    k_prep  <<<nGrid, T>>>((const int*)ei);
    k_deg   <<<eGrid, T>>>(ei);
    k_alloc <<<nGrid, T>>>(batch);
    k_bucket<<<eGrid, T>>>();
    k_cnt   <<<nGrid, T>>>(batch);

    const int mmGrid = (NN + MM_ROWS - 1) / MM_ROWS;   // 391
    const int gGrid  = (NN * 32 + T - 1) / T;          // 1 warp/node

    // layer 0
    k_matmul   <<<mmGrid, T>>>(0, x, W_in);
    k_gather_ln<<<gGrid, T>>>(b_in, ln_in_w, ln_in_b, 0, batch);
    // hidden layers (second one is the last -> fold pooling)
    for (int i = 0; i < 2; i++) {
        k_matmul   <<<mmGrid, T>>>(1, nullptr, W_h + i * DD * DD);
        k_gather_ln<<<gGrid, T>>>(b_h + i * DD, ln_h_w + i * DD, ln_h_b + i * DD,
                                  i == 1, batch);
    }
    k_final<<<NG, DOUT>>>(W_out, b_out, out);
}

// round 17
// speedup vs baseline: 1.0262x; 1.0262x over previous
#include <cuda_runtime.h>
#include <cuda_bf16.h>
#include <cuda_fp16.h>
#include <mma.h>
#include <cstdint>

using namespace nvcuda;

#define NN 50000
#define NE 800000
#define NG 512
#define DD 64
#define DOUT 32
#define LN_EPS 1e-5f
#define MM_ROWS 128

// ---------------- scratch (static device globals; 16B aligned) --------------
__device__ int g_is64;                            // 1 if index inputs are int64
__device__ int g_alloc;                           // CSR allocation cursor
__device__ __align__(16) int    g_edeg[NN];       // edge in-degree (no self loop)
__device__ __align__(16) float  g_dinv[NN];
__device__ __align__(16) int    g_src[NE];
__device__ __align__(16) int    g_dst[NE];
__device__ __align__(16) int    g_rank[NE];       // edge's rank within its dst row
__device__ __align__(16) int    g_rowstart[NN];   // CSR row offsets (unordered alloc)
__device__ __align__(16) int2   g_csr[NE];        // CSR: {src, weight bits}
__device__ __align__(16) __half g_h[NN * DD];     // layer activations (fp16)
__device__ __align__(16) __half g_hw[NN * DD];    // h @ W (fp16)
__device__ __align__(16) float  g_pool[NG * DD];
__device__ __align__(16) float  g_cnt[NG];

// ---------------- helpers ---------------------------------------------------
__device__ __forceinline__ float warp_sum(float v) {
    #pragma unroll
    for (int o = 16; o > 0; o >>= 1) v += __shfl_xor_sync(0xffffffffu, v, o);
    return v;
}
__device__ __forceinline__ int clampi(int v, int hi) {   // [0, hi)
    return v < 0 ? 0 : (v >= hi ? hi - 1 : v);
}
__device__ __forceinline__ int read_idx(const void* p, int i) {
    if (g_is64) return (int)((const long long*)p)[i];
    return ((const int*)p)[i];
}

// ---------------- setup kernels ---------------------------------------------
__global__ void k_prep(const int* __restrict__ raw) {
    int i = blockIdx.x * blockDim.x + threadIdx.x;
    if (i < NN) g_edeg[i] = 0;
    if (i < NG) g_cnt[i] = 0.0f;
    if (i == 0) g_alloc = 0;
    if (blockIdx.x == 0) {
        __shared__ int any;
        if (threadIdx.x == 0) any = 0;
        __syncthreads();
        if (raw[2 * threadIdx.x + 1] != 0) atomicOr(&any, 1);
        __syncthreads();
        if (threadIdx.x == 0) g_is64 = (any == 0) ? 1 : 0;
    }
}

// histogram; the returned old count IS this edge's stable rank in its dst row.
__global__ void k_deg(const void* __restrict__ ei) {
    int e = blockIdx.x * blockDim.x + threadIdx.x;
    if (e >= NE) return;
    int s = clampi(read_idx(ei, e), NN);
    int d = clampi(read_idx(ei, NE + e), NN);
    g_src[e] = s;
    g_dst[e] = d;
    g_rank[e] = atomicAdd(&g_edeg[d], 1);
}

// CSR slot allocation (order-free) + dinv + pool zero + graph-size histogram.
__global__ void k_alloc(const void* __restrict__ batch) {
    int i = blockIdx.x * blockDim.x + threadIdx.x;
    if (i < NG * DD) g_pool[i] = 0.0f;
    if (i >= NN) return;
    int d = g_edeg[i];
    g_dinv[i] = rsqrtf((float)(d + 1));   // +1 self loop
    g_rowstart[i] = atomicAdd(&g_alloc, d);
    atomicAdd(&g_cnt[clampi(read_idx(batch, i), NG)], 1.0f);
}

// atomic-free bucket: pos = rowstart[dst] + rank; store {src, fp32 weight}.
__global__ void k_bucket() {
    int e = blockIdx.x * blockDim.x + threadIdx.x;
    if (e >= NE) return;
    int s = g_src[e];
    int d = g_dst[e];
    float w = g_dinv[s] * g_dinv[d];
    int pos = g_rowstart[d] + g_rank[e];
    g_csr[pos] = make_int2(s, __float_as_int(w));
}

// ---------------- GEMM: g_hw = in @ W via wmma (HMMA fp16 -> fp32 acc) ------
__global__ void k_matmul(int use_h, const float* __restrict__ xin,
                         const float* __restrict__ W) {
    __shared__ __align__(16) char sbuf[128 * 72 * 4];
    __half (*As)[72] = reinterpret_cast<__half (*)[72]>(sbuf);
    __half (*Bs)[72] = reinterpret_cast<__half (*)[72]>(sbuf + 128 * 72 * 2);
    float  (*Cs)[72] = reinterpret_cast<float  (*)[72]>(sbuf);

    int t = threadIdx.x;
    int base = blockIdx.x * MM_ROWS;
    int row = t >> 1;
    int part = (t & 1) * 32;
    int grow = base + row;

    if (grow < NN) {
        if (use_h) {
            const int4* src = reinterpret_cast<const int4*>(&g_h[grow * DD + part]);
            int4* dst = reinterpret_cast<int4*>(&As[row][part]);
            #pragma unroll
            for (int i = 0; i < 4; i++) dst[i] = src[i];
        } else {
            const float4* src = reinterpret_cast<const float4*>(&xin[grow * DD + part]);
            __half2* dst = reinterpret_cast<__half2*>(&As[row][part]);
            #pragma unroll
            for (int i = 0; i < 8; i++) {
                float4 v = src[i];
                dst[2 * i]     = __floats2half2_rn(v.x, v.y);
                dst[2 * i + 1] = __floats2half2_rn(v.z, v.w);
            }
        }
    } else {
        int4 z = make_int4(0, 0, 0, 0);
        int4* dst = reinterpret_cast<int4*>(&As[row][part]);
        #pragma unroll
        for (int i = 0; i < 4; i++) dst[i] = z;
    }
    if (t < 128) {
        int brow = t >> 1;
        int bpart = (t & 1) * 32;
        const float4* src = reinterpret_cast<const float4*>(&W[brow * DD + bpart]);
        __half2* dst = reinterpret_cast<__half2*>(&Bs[brow][bpart]);
        #pragma unroll
        for (int i = 0; i < 8; i++) {
            float4 v = src[i];
            dst[2 * i]     = __floats2half2_rn(v.x, v.y);
            dst[2 * i + 1] = __floats2half2_rn(v.z, v.w);
        }
    }
    __syncthreads();

    int w = t >> 5;
    wmma::fragment<wmma::accumulator, 16, 16, 16, float> acc[4];
    #pragma unroll
    for (int n = 0; n < 4; n++) wmma::fill_fragment(acc[n], 0.0f);
    #pragma unroll
    for (int k = 0; k < 4; k++) {
        wmma::fragment<wmma::matrix_a, 16, 16, 16, __half, wmma::row_major> af;
        wmma::load_matrix_sync(af, &As[w * 16][k * 16], 72);
        #pragma unroll
        for (int n = 0; n < 4; n++) {
            wmma::fragment<wmma::matrix_b, 16, 16, 16, __half, wmma::row_major> bf;
            wmma::load_matrix_sync(bf, &Bs[k * 16][n * 16], 72);
            wmma::mma_sync(acc[n], af, bf, acc[n]);
        }
    }
    __syncthreads();
    #pragma unroll
    for (int n = 0; n < 4; n++)
        wmma::store_matrix_sync(&Cs[w * 16][n * 16], acc[n], 72, wmma::mem_row_major);
    __syncthreads();

    if (grow < NN) {
        __half2* dst = reinterpret_cast<__half2*>(&g_hw[grow * DD + part]);
        #pragma unroll
        for (int i = 0; i < 16; i++)
            dst[i] = __floats2half2_rn(Cs[row][part + 2 * i], Cs[row][part + 2 * i + 1]);
    }
}

// ---------------- fused gather + bias + LN + ReLU (+ pool on last) ----------
// one warp per node; lane handles cols 2*lane, 2*lane+1. No smem, no barriers.
__global__ void k_gather_ln(const float* __restrict__ b,
                            const float* __restrict__ lw,
                            const float* __restrict__ lb,
                            int last, const void* __restrict__ batch) {
    int n = (blockIdx.x * blockDim.x + threadIdx.x) >> 5;
    int lane = threadIdx.x & 31;
    if (n >= NN) return;

    const __half2* hw2 = reinterpret_cast<const __half2*>(g_hw);

    float ws = g_dinv[n]; ws *= ws;
    float2 bb = reinterpret_cast<const float2*>(b)[lane];
    float2 self = __half22float2(hw2[n * 32 + lane]);
    float a0 = bb.x + ws * self.x;
    float a1 = bb.y + ws * self.y;

    int beg = g_rowstart[n];
    int cnt = g_edeg[n];
    #pragma unroll 8
    for (int j = 0; j < cnt; j++) {
        int2 sw = g_csr[beg + j];
        float w = __int_as_float(sw.y);
        float2 v = __half22float2(hw2[sw.x * 32 + lane]);
        a0 += w * v.x;
        a1 += w * v.y;
    }

    float mu = warp_sum(a0 + a1) * (1.0f / DD);
    float d0 = a0 - mu, d1 = a1 - mu;
    float var = warp_sum(d0 * d0 + d1 * d1) * (1.0f / DD);
    float rs = rsqrtf(var + LN_EPS);
    float2 w2 = reinterpret_cast<const float2*>(lw)[lane];
    float2 lb2 = reinterpret_cast<const float2*>(lb)[lane];
    float o0 = fmaxf(d0 * rs * w2.x + lb2.x, 0.0f);
    float o1 = fmaxf(d1 * rs * w2.y + lb2.y, 0.0f);
    reinterpret_cast<__half2*>(g_h)[n * 32 + lane] = __floats2half2_rn(o0, o1);

    if (last) {
        int g = clampi(read_idx(batch, n), NG);
        atomicAdd(&g_pool[g * DD + 2 * lane],     o0);
        atomicAdd(&g_pool[g * DD + 2 * lane + 1], o1);
    }
}

// ---------------- output projection ------------------------------------------
__global__ void k_final(const float* __restrict__ Wo, const float* __restrict__ bo,
                        float* __restrict__ out) {
    int g = blockIdx.x;
    int j = threadIdx.x;          // 0..31
    float inv = 1.0f / fmaxf(g_cnt[g], 1.0f);
    float acc = bo[j];
    #pragma unroll
    for (int k = 0; k < DD; k++)
        acc += g_pool[g * DD + k] * inv * Wo[k * DOUT + j];
    out[g * DOUT + j] = acc;
}

// ---------------- launch -----------------------------------------------------
extern "C" void kernel_launch(void* const* d_in, const int* in_sizes, int n_in,
                              void* d_out, int out_size) {
    const float* x      = (const float*)d_in[0];
    const void*  ei     = d_in[1];                 // int32 or int64 (probed)
    const void*  batch  = d_in[2];
    const float* W_in   = (const float*)d_in[3];
    const float* b_in   = (const float*)d_in[4];
    const float* ln_in_w= (const float*)d_in[5];
    const float* ln_in_b= (const float*)d_in[6];
    const float* W_h    = (const float*)d_in[7];   // [2,64,64]
    const float* b_h    = (const float*)d_in[8];   // [2,64]
    const float* ln_h_w = (const float*)d_in[9];   // [2,64]
    const float* ln_h_b = (const float*)d_in[10];  // [2,64]
    const float* W_out  = (const float*)d_in[11];
    const float* b_out  = (const float*)d_in[12];
    float* out = (float*)d_out;

    const int T = 256;
    const int nGrid = (NN + T - 1) / T;
    const int eGrid = (NE + T - 1) / T;

    // CSR + norm build (once per call)
    k_prep  <<<nGrid, T>>>((const int*)ei);
    k_deg   <<<eGrid, T>>>(ei);
    k_alloc <<<nGrid, T>>>(batch);
    k_bucket<<<eGrid, T>>>();

    const int mmGrid = (NN + MM_ROWS - 1) / MM_ROWS;   // 391
    const int gGrid  = (NN * 32 + T - 1) / T;          // 1 warp/node

    // layer 0
    k_matmul   <<<mmGrid, T>>>(0, x, W_in);
    k_gather_ln<<<gGrid, T>>>(b_in, ln_in_w, ln_in_b, 0, batch);
    // hidden layers (second one is the last -> fold pooling)
    for (int i = 0; i < 2; i++) {
        k_matmul   <<<mmGrid, T>>>(1, nullptr, W_h + i * DD * DD);
        k_gather_ln<<<gGrid, T>>>(b_h + i * DD, ln_h_w + i * DD, ln_h_b + i * DD,
                                  i == 1, batch);
    }
    k_final<<<NG, DOUT>>>(W_out, b_out, out);
}